// round 12
// baseline (speedup 1.0000x reference)
#include <cuda_runtime.h>
#include <cuda_bf16.h>
#include <cstdint>

#define BATCH 2048
#define VOCAB 50000
#define EMB   100
#define CTX   10
#define KP    112          // K padded to 112 bf16 (7 x k16 mma steps)
#define VP    50176        // 784 * 64
#define NT    784          // number of 64-row B tiles
#define BM    128
#define BN    64
#define NSLICE 27
#define NCTA  (NSLICE * 16)   // 432 CTAs = one resident wave at 3 CTAs/SM
#define STRB   240         // smem row stride bytes (224B data + 16 pad)
#define ABYTES (BM * STRB) // 30720
#define BBYTES (BN * STRB) // 15360
#define SMEM_TOTAL (ABYTES + 2 * BBYTES)  // 61440

// Scratch (device globals, zero-init at module load)
__device__ __align__(16) __nv_bfloat16  g_hb[BATCH * KP];   // h, bf16
__device__ __align__(16) __nv_bfloat16  g_ub[VP * KP];      // emb_u * 0.5, bf16
__device__ float     g_negsum[BATCH];
__device__ float     g_pos[BATCH];
__device__ unsigned  g_ready;   // monotonic production counter
__device__ unsigned  g_done;    // monotonic completion counter
__device__ unsigned  g_epoch;   // run counter (bumped by last CTA each run)

__device__ __forceinline__ uint32_t s2u(const void* p) {
    uint32_t a;
    asm("{ .reg .u64 t; cvta.to.shared.u64 t, %1; cvt.u32.u64 %0, t; }" : "=r"(a) : "l"(p));
    return a;
}
__device__ __forceinline__ float tanh_approx(float x) {
    float y;
    asm("tanh.approx.f32 %0, %1;" : "=f"(y) : "f"(x));
    return y;
}
__device__ __forceinline__ void cpa16(uint32_t dst, const void* src) {
    asm volatile("cp.async.cg.shared.global [%0], [%1], 16;" :: "r"(dst), "l"(src));
}
__device__ __forceinline__ void ldsm4(uint32_t& r0, uint32_t& r1, uint32_t& r2,
                                      uint32_t& r3, uint32_t addr) {
    asm volatile("ldmatrix.sync.aligned.m8n8.x4.shared.b16 {%0,%1,%2,%3}, [%4];"
                 : "=r"(r0), "=r"(r1), "=r"(r2), "=r"(r3) : "r"(addr));
}
__device__ __forceinline__ uint32_t bfpack(float lo, float hi) {
    uint32_t r;
    asm("cvt.rn.bf16x2.f32 %0, %1, %2;" : "=r"(r) : "f"(hi), "f"(lo));
    return r;
}
__device__ __forceinline__ unsigned ldacq(const unsigned* p) {
    unsigned v;
    asm volatile("ld.acquire.gpu.b32 %0, [%1];" : "=r"(v) : "l"(p) : "memory");
    return v;
}

// ---------------------------------------------------------------------------
// Single fused persistent kernel. All 432 CTAs co-resident.
//  Phase A: s<4  -> produce h block rows [mbase+s*32, +32), pos, zero negsum
//           s>=4 -> convert assigned U tiles (j = (s-4) + 23*m + 368*k) to bf16
//  Rendezvous: ready-counter spin (epoch-scaled target, no reset needed)
//  Phase B: R11 gemm mainloop (bf16 mma + tanh-sum epilogue)
//  Tail: last CTA (done-counter) reduces loss, writes out, bumps epoch
// ---------------------------------------------------------------------------
__global__ void __launch_bounds__(256, 3) k_fused(const int* __restrict__ x,
                                                  const int* __restrict__ y,
                                                  const float* __restrict__ emb_v,
                                                  const float* __restrict__ emb_u,
                                                  float* __restrict__ out) {
    extern __shared__ __align__(16) char smem[];
    __shared__ int sfin;
    uint32_t sbase = s2u(smem);
    int t = threadIdx.x, w = t >> 5, lane = t & 31;
    int g = lane >> 2, tig = lane & 3;
    int s = blockIdx.x, m = blockIdx.y;
    int mbase = m * BM;
    unsigned E = *(volatile unsigned*)&g_epoch;

    // ---------------- Phase A: production (unconditional, deadlock-free) ----
    if (s < 4) {
        // h producer: 32 rows, 8 threads per row (14 cols each)
        int r = t >> 3, oct = t & 7;
        int b = mbase + s * 32 + r;
        int cx[CTX];
#pragma unroll
        for (int c = 0; c < CTX; c++) cx[c] = x[b * CTX + c];
        const float* uy = emb_u + (size_t)y[b] * EMB;
        int c0 = oct * 14;
        float pacc = 0.0f;
        uint32_t* dst = (uint32_t*)g_hb + (size_t)b * (KP / 2) + oct * 7;
#pragma unroll
        for (int p = 0; p < 7; p++) {
            float v0 = 0.0f, v1 = 0.0f;
            int col0 = c0 + 2 * p, col1 = col0 + 1;
            if (col0 < EMB) {
#pragma unroll
                for (int i = 0; i < CTX; i++) v0 += emb_v[(size_t)cx[i] * EMB + col0];
                v0 *= 0.1f; pacc += v0 * uy[col0];
            }
            if (col1 < EMB) {
#pragma unroll
                for (int i = 0; i < CTX; i++) v1 += emb_v[(size_t)cx[i] * EMB + col1];
                v1 *= 0.1f; pacc += v1 * uy[col1];
            }
            dst[p] = bfpack(v0, v1);   // h unscaled (B carries the 0.5)
        }
        pacc += __shfl_xor_sync(0xffffffffu, pacc, 1);
        pacc += __shfl_xor_sync(0xffffffffu, pacc, 2);
        pacc += __shfl_xor_sync(0xffffffffu, pacc, 4);
        if (oct == 0) {
            float d = pacc;
            float ls = (d >= 0.0f) ? -log1pf(expf(-d)) : d - log1pf(expf(d));
            g_pos[b] = -ls;
        }
        if (t < 32) g_negsum[mbase + s * 32 + t] = 0.0f;
    } else {
        // B producer: up to 3 tiles of 64 U rows each -> bf16 * 0.5, padded
#pragma unroll
        for (int k = 0; k < 3; k++) {
            int j = (s - 4) + 23 * m + 368 * k;
            if (j < NT) {
#pragma unroll
                for (int i = 0; i < 7; i++) {
                    int unit = t + 256 * i;        // 1792 uint2 units per tile
                    int row = unit / 28, c = unit % 28;
                    int v = j * 64 + row, k4 = c * 4;
                    uint2 o2 = {0u, 0u};
                    if (v < VOCAB && k4 < EMB) {   // k4 <= 96 -> float4 in-bounds
                        float4 f = *(const float4*)(emb_u + (size_t)v * EMB + k4);
                        o2.x = bfpack(0.5f * f.x, 0.5f * f.y);
                        o2.y = bfpack(0.5f * f.z, 0.5f * f.w);
                    }
                    ((uint2*)g_ub)[(size_t)v * 28 + c] = o2;
                }
            }
        }
    }
    __threadfence();
    __syncthreads();
    if (t == 0) atomicAdd(&g_ready, 1u);
    unsigned tgt = (E + 1u) * (unsigned)NCTA;
    while (ldacq(&g_ready) < tgt) __nanosleep(200);

    // ---------------- Phase B: gemm mainloop (R11) --------------------------
    int t0 = (s * NT) / NSLICE;
    int t1 = ((s + 1) * NT) / NSLICE;
    int arow0 = (w >> 1) * 32;
    int brow0 = (w & 1) * 32;
    uint32_t aoff0 = sbase + (arow0 + (lane & 15)) * STRB + (lane >> 4) * 16;
    uint32_t boff0 = (brow0 + ((lane >> 4) << 3) + (lane & 7)) * STRB
                   + ((lane >> 3) & 1) * 16;

    const uint4* gA = (const uint4*)(g_hb + (size_t)mbase * KP);
#pragma unroll
    for (int i = 0; i < 7; i++) {
        int idx = t + i * 256;
        int r = idx / 14, c = idx % 14;
        *(uint4*)(smem + r * STRB + c * 16) = gA[idx];
    }
    {
        const char* gB = (const char*)(g_ub + (size_t)t0 * BN * KP);
        uint32_t sb = sbase + ABYTES;
#pragma unroll
        for (int i = 0; i < 4; i++) {
            int idx = t + i * 256;
            if (idx < BN * 14) {
                int r = idx / 14, c = idx % 14;
                cpa16(sb + r * STRB + c * 16, gB + idx * 16);
            }
        }
        asm volatile("cp.async.commit_group;" ::: "memory");
    }

    float rs[4] = {0.0f, 0.0f, 0.0f, 0.0f};

    for (int j = t0; j < t1; j++) {
        int par = (j - t0) & 1;
        asm volatile("cp.async.wait_group 0;" ::: "memory");
        __syncthreads();
        if (j + 1 < t1) {
            const char* gB = (const char*)(g_ub + (size_t)(j + 1) * BN * KP);
            uint32_t sb = sbase + ABYTES + (par ^ 1) * BBYTES;
#pragma unroll
            for (int i = 0; i < 4; i++) {
                int idx = t + i * 256;
                if (idx < BN * 14) {
                    int r = idx / 14, c = idx % 14;
                    cpa16(sb + r * STRB + c * 16, gB + idx * 16);
                }
            }
            asm volatile("cp.async.commit_group;" ::: "memory");
        }

        uint32_t bbuf = sbase + ABYTES + par * BBYTES + boff0;
        float acc[2][2][2][4];
#pragma unroll
        for (int im = 0; im < 2; im++)
#pragma unroll
            for (int jn = 0; jn < 2; jn++)
#pragma unroll
                for (int i2 = 0; i2 < 2; i2++)
#pragma unroll
                    for (int q = 0; q < 4; q++) acc[im][jn][i2][q] = 0.0f;

#pragma unroll
        for (int ks = 0; ks < 7; ks++) {
            int kb = ks * 32;
            uint32_t a[2][4], b[2][4];
#pragma unroll
            for (int im = 0; im < 2; im++)
                ldsm4(a[im][0], a[im][1], a[im][2], a[im][3],
                      aoff0 + im * 16 * STRB + kb);
#pragma unroll
            for (int jn = 0; jn < 2; jn++)
                ldsm4(b[jn][0], b[jn][1], b[jn][2], b[jn][3],
                      bbuf + jn * 16 * STRB + kb);
#pragma unroll
            for (int im = 0; im < 2; im++)
#pragma unroll
                for (int jn = 0; jn < 2; jn++)
#pragma unroll
                    for (int i2 = 0; i2 < 2; i2++)
                        asm volatile(
                            "mma.sync.aligned.m16n8k16.row.col.f32.bf16.bf16.f32 "
                            "{%0,%1,%2,%3}, {%4,%5,%6,%7}, {%8,%9}, {%0,%1,%2,%3};"
                            : "+f"(acc[im][jn][i2][0]), "+f"(acc[im][jn][i2][1]),
                              "+f"(acc[im][jn][i2][2]), "+f"(acc[im][jn][i2][3])
                            : "r"(a[im][0]), "r"(a[im][1]),
                              "r"(a[im][2]), "r"(a[im][3]),
                              "r"(b[jn][2 * i2]), "r"(b[jn][2 * i2 + 1]));
        }

#pragma unroll
        for (int im = 0; im < 2; im++)
#pragma unroll
            for (int jn = 0; jn < 2; jn++)
#pragma unroll
                for (int i2 = 0; i2 < 2; i2++)
#pragma unroll
                    for (int q = 0; q < 4; q++)
                        rs[im * 2 + (q >> 1)] += tanh_approx(acc[im][jn][i2][q]);
    }

#pragma unroll
    for (int i = 0; i < 4; i++) {
        rs[i] += __shfl_xor_sync(0xffffffff, rs[i], 1);
        rs[i] += __shfl_xor_sync(0xffffffff, rs[i], 2);
    }
    if (tig == 0) {
#pragma unroll
        for (int im = 0; im < 2; im++)
#pragma unroll
            for (int h = 0; h < 2; h++) {
                int row = mbase + arow0 + im * 16 + h * 8 + g;
                atomicAdd(&g_negsum[row], rs[im * 2 + h]);
            }
    }

    // ---------------- Tail: last CTA reduces -------------------------------
    __threadfence();
    __syncthreads();
    if (t == 0) {
        unsigned old = atomicAdd(&g_done, 1u);
        sfin = (((old + 1u) % (unsigned)NCTA) == 0u);
    }
    __syncthreads();
    if (sfin) {
        float* sr = (float*)smem;
        float v = 0.0f;
        for (int i = t; i < BATCH; i += 256)
            v += __ldcg(&g_pos[i])
               + logf(0.5f * (float)VOCAB - 0.5f * __ldcg(&g_negsum[i]));
        sr[t] = v;
        __syncthreads();
        for (int o = 128; o; o >>= 1) {
            if (t < o) sr[t] += sr[t + o];
            __syncthreads();
        }
        if (t == 0) {
            out[0] = sr[0] / (float)BATCH;
            *(volatile unsigned*)&g_epoch = E + 1u;   // arm next run
        }
    }
}

// ---------------------------------------------------------------------------
extern "C" void kernel_launch(void* const* d_in, const int* in_sizes, int n_in,
                              void* d_out, int out_size) {
    const int*   x     = (const int*)d_in[0];
    const int*   y     = (const int*)d_in[1];
    const float* emb_v = (const float*)d_in[2];
    const float* emb_u = (const float*)d_in[3];

    cudaFuncSetAttribute(k_fused, cudaFuncAttributeMaxDynamicSharedMemorySize, SMEM_TOTAL);
    dim3 grid(NSLICE, BATCH / BM);  // 27 x 16 = 432 CTAs, all co-resident
    k_fused<<<grid, 256, SMEM_TOTAL>>>(x, y, emb_v, emb_u, (float*)d_out);
}

// round 13
// speedup vs baseline: 1.2762x; 1.2762x over previous
#include <cuda_runtime.h>
#include <cuda_bf16.h>
#include <cstdint>

#define BATCH 2048
#define VOCAB 50000
#define EMB   100
#define CTX   10
#define KP    112          // K padded to 112 bf16 (7 x k16 mma steps)
#define VP    50176        // 784 * 64
#define NT    784          // number of 64-row B tiles
#define BM    128
#define BN    64
#define NSLICE 27
#define NCTA  (NSLICE * 16)   // 432 CTAs, all co-resident at 3 CTAs/SM
#define STRB   240
#define ABYTES (BM * STRB) // 30720
#define BBYTES (BN * STRB) // 15360
#define SMEM_TOTAL (ABYTES + 2 * BBYTES)  // 61440

// Scratch (device globals, zero-init at module load)
__device__ __align__(16) __nv_bfloat16  g_hb[BATCH * KP];   // h, bf16 (pads stay 0)
__device__ __align__(16) __nv_bfloat16  g_ub[VP * KP];      // emb_u * 0.5, bf16
__device__ float     g_negsum[BATCH];
__device__ float     g_pos[BATCH];
__device__ unsigned  g_tflag[NT];    // per-tile release flag (== epoch+1 when ready)
__device__ unsigned  g_hcnt[16];     // per-m h-producer arrival counter
__device__ unsigned  g_done;
__device__ unsigned  g_epoch;

__device__ __forceinline__ uint32_t s2u(const void* p) {
    uint32_t a;
    asm("{ .reg .u64 t; cvta.to.shared.u64 t, %1; cvt.u32.u64 %0, t; }" : "=r"(a) : "l"(p));
    return a;
}
__device__ __forceinline__ float tanh_approx(float x) {
    float y;
    asm("tanh.approx.f32 %0, %1;" : "=f"(y) : "f"(x));
    return y;
}
__device__ __forceinline__ void cpa16(uint32_t dst, const void* src) {
    asm volatile("cp.async.cg.shared.global [%0], [%1], 16;" :: "r"(dst), "l"(src));
}
__device__ __forceinline__ void ldsm4(uint32_t& r0, uint32_t& r1, uint32_t& r2,
                                      uint32_t& r3, uint32_t addr) {
    asm volatile("ldmatrix.sync.aligned.m8n8.x4.shared.b16 {%0,%1,%2,%3}, [%4];"
                 : "=r"(r0), "=r"(r1), "=r"(r2), "=r"(r3) : "r"(addr));
}
__device__ __forceinline__ uint32_t bfpack(float lo, float hi) {
    uint32_t r;
    asm("cvt.rn.bf16x2.f32 %0, %1, %2;" : "=r"(r) : "f"(hi), "f"(lo));
    return r;
}
__device__ __forceinline__ unsigned ldacq(const unsigned* p) {
    unsigned v;
    asm volatile("ld.acquire.gpu.b32 %0, [%1];" : "=r"(v) : "l"(p) : "memory");
    return v;
}

// ---------------------------------------------------------------------------
// Persistent fused kernel, 432 co-resident CTAs, fine-grained flags:
//  1. each CTA converts its OWNED B tiles (j = s + 27q, owner m = q%16),
//     sets per-tile flag -> consumers unblock tile-by-tile
//  2. each CTA produces ~5 h rows of its own m-block (+pos, negsum=0);
//     per-m counter (27 arrivals) gates the m-group only
//  3. mainloop = R11 gemm (bf16 mma + tanh-sum), spin on tile flag pre-prefetch
//  4. done-counter tail: last CTA reduces loss, writes out, bumps epoch
// ---------------------------------------------------------------------------
__global__ void __launch_bounds__(256, 3) k_fused(const int* __restrict__ x,
                                                  const int* __restrict__ y,
                                                  const float* __restrict__ emb_v,
                                                  const float* __restrict__ emb_u,
                                                  float* __restrict__ out) {
    extern __shared__ __align__(16) char smem[];
    __shared__ int sfin;
    uint32_t sbase = s2u(smem);
    int t = threadIdx.x, w = t >> 5, lane = t & 31;
    int g = lane >> 2, tig = lane & 3;
    int s = blockIdx.x, m = blockIdx.y;
    int mbase = m * BM;
    unsigned E = *(volatile unsigned*)&g_epoch;

    // ---- 1. Convert owned B tiles (emb_u * 0.5 -> bf16, padded) -----------
    for (int q = m; q < 30; q += 16) {
        int j = s + 27 * q;
        if (j < NT) {
#pragma unroll
            for (int i = 0; i < 7; i++) {
                int unit = t + 256 * i;        // 1792 uint2 units per tile
                int row = unit / 28, c = unit % 28;
                int v = j * 64 + row, k4 = c * 4;
                uint2 o2 = {0u, 0u};
                if (v < VOCAB && k4 < EMB) {   // k4 <= 96 -> float4 in-bounds
                    float4 f = *(const float4*)(emb_u + (size_t)v * EMB + k4);
                    o2.x = bfpack(0.5f * f.x, 0.5f * f.y);
                    o2.y = bfpack(0.5f * f.z, 0.5f * f.w);
                }
                ((uint2*)g_ub)[(size_t)v * 28 + c] = o2;
            }
            __threadfence();
            __syncthreads();
            if (t == 0) atomicExch(&g_tflag[j], E + 1u);
        }
    }

    // ---- 2. Produce h rows [mbase+lo, mbase+hi) (one warp per row) --------
    int lo = (s * BM) / NSLICE, hi = ((s + 1) * BM) / NSLICE;
    if (w < hi - lo) {
        int b = mbase + lo + w;
        int cx[CTX];
#pragma unroll
        for (int c = 0; c < CTX; c++) cx[c] = x[b * CTX + c];
        const float* uy = emb_u + (size_t)y[b] * EMB;
        float pacc = 0.0f;
#pragma unroll
        for (int p = 0; p < 4; p++) {
            int col = lane + 32 * p;
            if (col < EMB) {
                float v = 0.0f;
#pragma unroll
                for (int i = 0; i < CTX; i++) v += emb_v[(size_t)cx[i] * EMB + col];
                v *= 0.1f;
                g_hb[(size_t)b * KP + col] = __float2bfloat16(v);
                pacc += v * uy[col];
            }
        }
#pragma unroll
        for (int o = 16; o; o >>= 1) pacc += __shfl_xor_sync(0xffffffffu, pacc, o);
        if (lane == 0) {
            float d = pacc;
            float ls = (d >= 0.0f) ? -log1pf(expf(-d)) : d - log1pf(expf(d));
            g_pos[b] = -ls;
            g_negsum[b] = 0.0f;
        }
    }
    __threadfence();
    __syncthreads();
    if (t == 0) {
        atomicAdd(&g_hcnt[m], 1u);
        unsigned tgt = (unsigned)NSLICE * (E + 1u);
        while (ldacq(&g_hcnt[m]) < tgt) __nanosleep(100);
    }
    __syncthreads();

    // ---- 3. GEMM mainloop (R11) -------------------------------------------
    int t0 = (s * NT) / NSLICE;
    int t1 = ((s + 1) * NT) / NSLICE;
    int arow0 = (w >> 1) * 32;
    int brow0 = (w & 1) * 32;
    uint32_t aoff0 = sbase + (arow0 + (lane & 15)) * STRB + (lane >> 4) * 16;
    uint32_t boff0 = (brow0 + ((lane >> 4) << 3) + (lane & 7)) * STRB
                   + ((lane >> 3) & 1) * 16;

    const uint4* gA = (const uint4*)(g_hb + (size_t)mbase * KP);
#pragma unroll
    for (int i = 0; i < 7; i++) {
        int idx = t + i * 256;
        int r = idx / 14, c = idx % 14;
        *(uint4*)(smem + r * STRB + c * 16) = gA[idx];
    }
    if (t == 0) { while (ldacq(&g_tflag[t0]) < E + 1u) __nanosleep(100); }
    __syncthreads();
    {
        const char* gB = (const char*)(g_ub + (size_t)t0 * BN * KP);
        uint32_t sb = sbase + ABYTES;
#pragma unroll
        for (int i = 0; i < 4; i++) {
            int idx = t + i * 256;
            if (idx < BN * 14) {
                int r = idx / 14, c = idx % 14;
                cpa16(sb + r * STRB + c * 16, gB + idx * 16);
            }
        }
        asm volatile("cp.async.commit_group;" ::: "memory");
    }

    float rs[4] = {0.0f, 0.0f, 0.0f, 0.0f};

    for (int j = t0; j < t1; j++) {
        int par = (j - t0) & 1;
        asm volatile("cp.async.wait_group 0;" ::: "memory");
        __syncthreads();
        if (j + 1 < t1) {
            if (t == 0) { while (ldacq(&g_tflag[j + 1]) < E + 1u) __nanosleep(100); }
            __syncthreads();
            const char* gB = (const char*)(g_ub + (size_t)(j + 1) * BN * KP);
            uint32_t sb = sbase + ABYTES + (par ^ 1) * BBYTES;
#pragma unroll
            for (int i = 0; i < 4; i++) {
                int idx = t + i * 256;
                if (idx < BN * 14) {
                    int r = idx / 14, c = idx % 14;
                    cpa16(sb + r * STRB + c * 16, gB + idx * 16);
                }
            }
            asm volatile("cp.async.commit_group;" ::: "memory");
        }

        uint32_t bbuf = sbase + ABYTES + par * BBYTES + boff0;
        float acc[2][2][2][4];
#pragma unroll
        for (int im = 0; im < 2; im++)
#pragma unroll
            for (int jn = 0; jn < 2; jn++)
#pragma unroll
                for (int i2 = 0; i2 < 2; i2++)
#pragma unroll
                    for (int q = 0; q < 4; q++) acc[im][jn][i2][q] = 0.0f;

#pragma unroll
        for (int ks = 0; ks < 7; ks++) {
            int kb = ks * 32;
            uint32_t a[2][4], b[2][4];
#pragma unroll
            for (int im = 0; im < 2; im++)
                ldsm4(a[im][0], a[im][1], a[im][2], a[im][3],
                      aoff0 + im * 16 * STRB + kb);
#pragma unroll
            for (int jn = 0; jn < 2; jn++)
                ldsm4(b[jn][0], b[jn][1], b[jn][2], b[jn][3],
                      bbuf + jn * 16 * STRB + kb);
#pragma unroll
            for (int im = 0; im < 2; im++)
#pragma unroll
                for (int jn = 0; jn < 2; jn++)
#pragma unroll
                    for (int i2 = 0; i2 < 2; i2++)
                        asm volatile(
                            "mma.sync.aligned.m16n8k16.row.col.f32.bf16.bf16.f32 "
                            "{%0,%1,%2,%3}, {%4,%5,%6,%7}, {%8,%9}, {%0,%1,%2,%3};"
                            : "+f"(acc[im][jn][i2][0]), "+f"(acc[im][jn][i2][1]),
                              "+f"(acc[im][jn][i2][2]), "+f"(acc[im][jn][i2][3])
                            : "r"(a[im][0]), "r"(a[im][1]),
                              "r"(a[im][2]), "r"(a[im][3]),
                              "r"(b[jn][2 * i2]), "r"(b[jn][2 * i2 + 1]));
        }

#pragma unroll
        for (int im = 0; im < 2; im++)
#pragma unroll
            for (int jn = 0; jn < 2; jn++)
#pragma unroll
                for (int i2 = 0; i2 < 2; i2++)
#pragma unroll
                    for (int q = 0; q < 4; q++)
                        rs[im * 2 + (q >> 1)] += tanh_approx(acc[im][jn][i2][q]);
    }

#pragma unroll
    for (int i = 0; i < 4; i++) {
        rs[i] += __shfl_xor_sync(0xffffffff, rs[i], 1);
        rs[i] += __shfl_xor_sync(0xffffffff, rs[i], 2);
    }
    if (tig == 0) {
#pragma unroll
        for (int im = 0; im < 2; im++)
#pragma unroll
            for (int h = 0; h < 2; h++) {
                int row = mbase + arow0 + im * 16 + h * 8 + g;
                atomicAdd(&g_negsum[row], rs[im * 2 + h]);
            }
    }

    // ---- 4. Tail: last CTA reduces ----------------------------------------
    __threadfence();
    __syncthreads();
    if (t == 0) {
        unsigned old = atomicAdd(&g_done, 1u);
        sfin = (((old + 1u) % (unsigned)NCTA) == 0u);
    }
    __syncthreads();
    if (sfin) {
        float* sr = (float*)smem;
        float v = 0.0f;
        for (int i = t; i < BATCH; i += 256)
            v += __ldcg(&g_pos[i])
               + logf(0.5f * (float)VOCAB - 0.5f * __ldcg(&g_negsum[i]));
        sr[t] = v;
        __syncthreads();
        for (int o = 128; o; o >>= 1) {
            if (t < o) sr[t] += sr[t + o];
            __syncthreads();
        }
        if (t == 0) {
            out[0] = sr[0] / (float)BATCH;
            *(volatile unsigned*)&g_epoch = E + 1u;
        }
    }
}

// ---------------------------------------------------------------------------
extern "C" void kernel_launch(void* const* d_in, const int* in_sizes, int n_in,
                              void* d_out, int out_size) {
    const int*   x     = (const int*)d_in[0];
    const int*   y     = (const int*)d_in[1];
    const float* emb_v = (const float*)d_in[2];
    const float* emb_u = (const float*)d_in[3];

    cudaFuncSetAttribute(k_fused, cudaFuncAttributeMaxDynamicSharedMemorySize, SMEM_TOTAL);
    dim3 grid(NSLICE, BATCH / BM);  // 27 x 16 = 432 CTAs, all co-resident
    k_fused<<<grid, 256, SMEM_TOTAL>>>(x, y, emb_v, emb_u, (float*)d_out);
}